// round 10
// baseline (speedup 1.0000x reference)
#include <cuda_runtime.h>
#include <cstdint>
#include <cstddef>

#define Bsz 8
#define Cc  32
#define Oo  64
#define Hh  64
#define Ww  64
#define Kk  9

constexpr int OTILE = 4;                  // o's per block (every thread owns all 4)
constexpr int SEG   = Ww * Kk;            // 576 floats per (o,c,h)
constexpr int WTILE = OTILE * SEG;        // 2304 floats per c (9216 B)
constexpr int XROWS = 3;
constexpr int XCOLP = 72;                 // [3]=col -1, [4..67]=cols 0..63, [68]=col 64
constexpr int XTILE = Bsz * XROWS * XCOLP;// 1728 floats per c (6912 B)
constexpr int SMEM_BYTES = 16 + (2 * WTILE + 2 * XTILE) * 4;   // 32272 B -> 7 CTAs/SM
constexpr int WC_STRIDE = Hh * SEG;
constexpr int XC_STRIDE = Hh * Ww;
constexpr uint32_t WSEG_BYTES = SEG * 4;  // 2304
constexpr uint32_t XROW_BYTES = Ww * 4;   // 256

typedef unsigned long long ull;

__device__ __forceinline__ ull pack2(float lo, float hi) {
    ull r; asm("mov.b64 %0, {%1, %2};" : "=l"(r) : "f"(lo), "f"(hi)); return r;
}
__device__ __forceinline__ void unpack2(float& lo, float& hi, ull v) {
    asm("mov.b64 {%0, %1}, %2;" : "=f"(lo), "=f"(hi) : "l"(v));
}
__device__ __forceinline__ void fma2(ull& d, ull a, ull b) {
    asm("fma.rn.f32x2 %0, %1, %2, %0;" : "+l"(d) : "l"(a), "l"(b));
}

__device__ __forceinline__ void mbar_init(uint32_t mbar, uint32_t cnt) {
    asm volatile("mbarrier.init.shared.b64 [%0], %1;" :: "r"(mbar), "r"(cnt) : "memory");
}
__device__ __forceinline__ void mbar_expect_tx(uint32_t mbar, uint32_t bytes) {
    asm volatile("mbarrier.arrive.expect_tx.shared.b64 _, [%0], %1;"
                 :: "r"(mbar), "r"(bytes) : "memory");
}
__device__ __forceinline__ void mbar_wait(uint32_t mbar, uint32_t parity) {
    asm volatile(
        "{\n\t.reg .pred P;\n\t"
        "W%=:\n\t"
        "mbarrier.try_wait.parity.acquire.cta.shared::cta.b64 P, [%0], %1, 0x989680;\n\t"
        "@!P bra W%=;\n\t}"
        :: "r"(mbar), "r"(parity) : "memory");
}
__device__ __forceinline__ void bulk_cp(uint32_t dst, const float* src,
                                        uint32_t bytes, uint32_t mbar) {
    asm volatile("cp.async.bulk.shared::cta.global.mbarrier::complete_tx::bytes "
                 "[%0], [%1], %2, [%3];"
                 :: "r"(dst), "l"(src), "r"(bytes), "r"(mbar) : "memory");
}

__global__ void __launch_bounds__(64, 7)
lc2d_kernel(const float* __restrict__ x,
            const float* __restrict__ wt,
            float* __restrict__ out)
{
    extern __shared__ float smem[];
    const uint32_t sbase = (uint32_t)__cvta_generic_to_shared(smem);
    float* wsm = smem + 4;                 // [2][WTILE]
    float* xsm = smem + 4 + 2 * WTILE;     // [2][XTILE]
    const uint32_t wsm_u = sbase + 16;
    const uint32_t xsm_u = sbase + 16 + 2 * WTILE * 4;
    const uint32_t mbar0 = sbase;
    const uint32_t mbar1 = sbase + 8;

    const int tid = threadIdx.x;           // 64 threads: one w column each
    const int w   = tid;
    const int h   = blockIdx.x;
    const int ob  = blockIdx.y * OTILE;

    // ---- one-time zero init: halo cols + OOB rows (bulk copies never touch these) ----
    #pragma unroll
    for (int i = 0; i < 2; i++) {
        int t = tid + i * 64;
        if (t < 96) {                      // cols 3 and 68 of every (buf,b,row)
            int bufsel = t / 48;
            int q      = t - bufsel * 48;
            int b      = q / 6;
            int rr     = q - b * 6;
            int r      = rr >> 1;
            int side   = rr & 1;
            xsm[bufsel * XTILE + (b * XROWS + r) * XCOLP + (side ? 68 : 3)] = 0.f;
        }
    }
    if (h == 0 || h == Hh - 1) {           // zero the single OOB row per b, both buffers
        int badrow = (h == 0) ? 0 : 2;
        #pragma unroll
        for (int i = 0; i < 16; i++) {
            int idx = tid + i * 64;        // 1024 floats: 2 bufs x 8 b x 64 cols
            int bufsel = idx >> 9;
            int rem    = idx & 511;
            int b      = rem >> 6;
            int col    = rem & 63;
            xsm[bufsel * XTILE + (b * XROWS + badrow) * XCOLP + 4 + col] = 0.f;
        }
    }

    // ---- staging roles ----
    // threads 32..35 (warp 1): weight segment seg = tid-32 (4 x 2304 B bulks)
    // threads  0..23 (warp 0): x row (b = tid/3, r = tid%3) (256 B bulks, if valid)
    const int  wseg   = tid - 32;
    const bool is_wst = (tid >= 32 && tid < 32 + OTILE);
    int  wsrc0 = 0; uint32_t wdst_off = 0;
    if (is_wst) {
        wsrc0    = (((ob + wseg) * Cc) * Hh + h) * SEG;
        wdst_off = (uint32_t)(wseg * SEG) * 4;
    }
    const bool is_xst = (tid < 24);
    bool xvalid = false; int xsrc0 = 0; uint32_t xdst_off = 0;
    if (is_xst) {
        int xb_ = tid / 3, xr_ = tid - (tid / 3) * 3;
        int grow = h - 1 + xr_;
        xvalid = (grow >= 0 && grow < Hh);
        xsrc0  = ((xb_ * Cc) * Hh + grow) * Ww;
        xdst_off = (uint32_t)((xb_ * XROWS + xr_) * XCOLP + 4) * 4;
    }
    const int nrows = XROWS - (h == 0) - (h == Hh - 1);
    const uint32_t TXBYTES = OTILE * WSEG_BYTES + (uint32_t)(nrows * Bsz) * XROW_BYTES;

    auto issue_bulks = [&](int c) {        // channel c -> buffer c&1
        const int buf = c & 1;
        const uint32_t mb = (buf ? mbar1 : mbar0);
        if (is_wst)
            bulk_cp(wsm_u + (uint32_t)buf * (WTILE * 4) + wdst_off,
                    wt + wsrc0 + c * WC_STRIDE, WSEG_BYTES, mb);
        if (is_xst && xvalid)
            bulk_cp(xsm_u + (uint32_t)buf * (XTILE * 4) + xdst_off,
                    x + xsrc0 + c * XC_STRIDE, XROW_BYTES, mb);
    };

    // prologue: arm both barriers strictly before any bulk issues
    if (tid == 0) {
        mbar_init(mbar0, 1);
        mbar_init(mbar1, 1);
        mbar_expect_tx(mbar0, TXBYTES);
        mbar_expect_tx(mbar1, TXBYTES);
    }
    __syncthreads();
    issue_bulks(0);
    issue_bulks(1);

    ull acc2[OTILE][4];
    #pragma unroll
    for (int oo = 0; oo < OTILE; oo++)
        #pragma unroll
        for (int bp = 0; bp < 4; bp++)
            acc2[oo][bp] = 0ull;

    for (int c = 0; c < Cc; c++) {
        const int cur = c & 1;
        mbar_wait(cur ? mbar1 : mbar0, (c >> 1) & 1);   // stage(c) complete (acquire)

        const float* wb = wsm + cur * WTILE + w * Kk;
        const float* xb = xsm + cur * XTILE + 3 + w;

        #pragma unroll
        for (int r = 0; r < 3; r++) {
            ull wr2[OTILE][3];
            #pragma unroll
            for (int oo = 0; oo < OTILE; oo++)
                #pragma unroll
                for (int kk = 0; kk < 3; kk++) {
                    float f = wb[oo * SEG + r * 3 + kk];
                    wr2[oo][kk] = pack2(f, f);
                }
            #pragma unroll
            for (int bp = 0; bp < 4; bp++) {
                const float* xlo = xb + (2 * bp)     * (XROWS * XCOLP) + r * XCOLP;
                const float* xhi = xb + (2 * bp + 1) * (XROWS * XCOLP) + r * XCOLP;
                ull xv2[3];
                #pragma unroll
                for (int kk = 0; kk < 3; kk++)
                    xv2[kk] = pack2(xlo[kk], xhi[kk]);
                #pragma unroll
                for (int oo = 0; oo < OTILE; oo++)
                    #pragma unroll
                    for (int kk = 0; kk < 3; kk++)
                        fma2(acc2[oo][bp], wr2[oo][kk], xv2[kk]);
            }
        }

        if (c + 2 < Cc) {
            // re-arm the consumed barrier BEFORE the CTA barrier that releases stagers
            if (tid == 0)
                mbar_expect_tx(cur ? mbar1 : mbar0, TXBYTES);
            __syncthreads();               // all threads done READING buffer `cur`
            issue_bulks(c + 2);            // refill just-consumed buffer
        }
    }

    // epilogue: coalesced stores (lanes = consecutive w)
    float* op = out + ((size_t)ob * Hh + h) * Ww + w;
    #pragma unroll
    for (int bp = 0; bp < 4; bp++)
        #pragma unroll
        for (int oo = 0; oo < OTILE; oo++) {
            float lo, hi;
            unpack2(lo, hi, acc2[oo][bp]);
            op[(size_t)((2 * bp)     * Oo + oo) * (Hh * Ww)] = lo;
            op[(size_t)((2 * bp + 1) * Oo + oo) * (Hh * Ww)] = hi;
        }
}

extern "C" void kernel_launch(void* const* d_in, const int* in_sizes, int n_in,
                              void* d_out, int out_size)
{
    const float* x  = (const float*)d_in[0];
    const float* wt = (const float*)d_in[1];
    float* out      = (float*)d_out;

    cudaFuncSetAttribute(lc2d_kernel,
                         cudaFuncAttributeMaxDynamicSharedMemorySize, SMEM_BYTES);
    cudaFuncSetAttribute(lc2d_kernel,
                         cudaFuncAttributePreferredSharedMemoryCarveout, 100);

    dim3 grid(Hh, Oo / OTILE);   // 64 x 16 = 1024 blocks of 64 threads
    lc2d_kernel<<<grid, 64, SMEM_BYTES>>>(x, wt, out);
}

// round 11
// speedup vs baseline: 1.4488x; 1.4488x over previous
#include <cuda_runtime.h>
#include <cstdint>
#include <cstddef>

#define Bsz 8
#define Cc  32
#define Oo  64
#define Hh  64
#define Ww  64
#define Kk  9

constexpr int OTILE = 16;                 // o's per block
constexpr int SEG   = Ww * Kk;            // 576 floats per (o,c,h)
constexpr int WTILE = OTILE * SEG;        // 9216 floats per c (36864 B)
constexpr int XROWS = 3;
constexpr int XCOLP = 72;                 // [3]=col -1, [4..67]=cols 0..63, [68]=col 64
constexpr int XTILE = Bsz * XROWS * XCOLP;// 1728 floats per c (6912 B)
constexpr int SMEM_BYTES = 16 + (2 * WTILE + 2 * XTILE) * 4;   // 87568 B -> 2 CTAs/SM
constexpr int WC_STRIDE = Hh * SEG;
constexpr int XC_STRIDE = Hh * Ww;
constexpr uint32_t WSEG_BYTES = SEG * 4;  // 2304
constexpr uint32_t XROW_BYTES = Ww * 4;   // 256

typedef unsigned long long ull;

__device__ __forceinline__ ull pack2(float lo, float hi) {
    ull r; asm("mov.b64 %0, {%1, %2};" : "=l"(r) : "f"(lo), "f"(hi)); return r;
}
__device__ __forceinline__ void unpack2(float& lo, float& hi, ull v) {
    asm("mov.b64 {%0, %1}, %2;" : "=f"(lo), "=f"(hi) : "l"(v));
}
__device__ __forceinline__ void fma2(ull& d, ull a, ull b) {
    asm("fma.rn.f32x2 %0, %1, %2, %0;" : "+l"(d) : "l"(a), "l"(b));
}

__device__ __forceinline__ void mbar_init(uint32_t mbar, uint32_t cnt) {
    asm volatile("mbarrier.init.shared.b64 [%0], %1;" :: "r"(mbar), "r"(cnt) : "memory");
}
__device__ __forceinline__ void mbar_expect_tx(uint32_t mbar, uint32_t bytes) {
    asm volatile("mbarrier.arrive.expect_tx.shared.b64 _, [%0], %1;"
                 :: "r"(mbar), "r"(bytes) : "memory");
}
__device__ __forceinline__ void mbar_wait(uint32_t mbar, uint32_t parity) {
    asm volatile(
        "{\n\t.reg .pred P;\n\t"
        "W%=:\n\t"
        "mbarrier.try_wait.parity.acquire.cta.shared::cta.b64 P, [%0], %1, 0x989680;\n\t"
        "@!P bra W%=;\n\t}"
        :: "r"(mbar), "r"(parity) : "memory");
}
__device__ __forceinline__ void bulk_cp(uint32_t dst, const float* src,
                                        uint32_t bytes, uint32_t mbar) {
    asm volatile("cp.async.bulk.shared::cta.global.mbarrier::complete_tx::bytes "
                 "[%0], [%1], %2, [%3];"
                 :: "r"(dst), "l"(src), "r"(bytes), "r"(mbar) : "memory");
}

__global__ void __launch_bounds__(256, 2)
lc2d_kernel(const float* __restrict__ x,
            const float* __restrict__ wt,
            float* __restrict__ out)
{
    extern __shared__ float smem[];
    const uint32_t sbase = (uint32_t)__cvta_generic_to_shared(smem);
    float* wsm = smem + 4;                 // [2][WTILE]
    float* xsm = smem + 4 + 2 * WTILE;     // [2][XTILE]
    const uint32_t wsm_u = sbase + 16;
    const uint32_t xsm_u = sbase + 16 + 2 * WTILE * 4;
    const uint32_t mbar0 = sbase;
    const uint32_t mbar1 = sbase + 8;

    const int tid = threadIdx.x;           // 256 threads
    const int w   = tid & 63;
    const int oq  = tid >> 6;              // 0..3
    const int h   = blockIdx.x;
    const int ob  = blockIdx.y * OTILE;
    const int o0  = ob + oq * 4;

    // ---- one-time zero init: halo cols + OOB rows (bulk copies never touch these) ----
    if (tid < 96) {                        // cols 3 and 68 of every (buf,b,row)
        int bufsel = tid / 48;
        int q      = tid - bufsel * 48;
        int b      = q / 6;
        int rr     = q - b * 6;
        int r      = rr >> 1;
        int side   = rr & 1;
        xsm[bufsel * XTILE + (b * XROWS + r) * XCOLP + (side ? 68 : 3)] = 0.f;
    }
    if (h == 0 || h == Hh - 1) {           // zero the single OOB row per b, both buffers
        int badrow = (h == 0) ? 0 : 2;
        #pragma unroll
        for (int i = 0; i < 4; i++) {
            int idx = tid + i * 256;       // 1024 floats: 2 bufs x 8 b x 64 cols
            int bufsel = idx >> 9;
            int rem    = idx & 511;
            int b      = rem >> 6;
            int col    = rem & 63;
            xsm[bufsel * XTILE + (b * XROWS + badrow) * XCOLP + 4 + col] = 0.f;
        }
    }

    // ---- staging roles ----
    // threads 64..79 (warp 2): weight segment seg = tid-64  (16 x 2304 B bulks)
    // threads  0..23 (warp 0): x row (b = tid/3, r = tid%3)  (256 B bulks, if valid)
    const int  wseg   = tid - 64;
    const bool is_wst = (tid >= 64 && tid < 64 + OTILE);
    int  wsrc0 = 0; uint32_t wdst_off = 0;
    if (is_wst) {
        wsrc0    = (((ob + wseg) * Cc) * Hh + h) * SEG;
        wdst_off = (uint32_t)(wseg * SEG) * 4;
    }
    const bool is_xst = (tid < 24);
    bool xvalid = false; int xsrc0 = 0; uint32_t xdst_off = 0;
    if (is_xst) {
        int xb_ = tid / 3, xr_ = tid - (tid / 3) * 3;
        int grow = h - 1 + xr_;
        xvalid = (grow >= 0 && grow < Hh);
        xsrc0  = ((xb_ * Cc) * Hh + grow) * Ww;
        xdst_off = (uint32_t)((xb_ * XROWS + xr_) * XCOLP + 4) * 4;
    }
    const int nrows = XROWS - (h == 0) - (h == Hh - 1);
    const uint32_t TXBYTES = OTILE * WSEG_BYTES + (uint32_t)(nrows * Bsz) * XROW_BYTES;

    auto issue_bulks = [&](int c) {        // channel c -> buffer c&1
        const int buf = c & 1;
        const uint32_t mb = (buf ? mbar1 : mbar0);
        if (is_wst)
            bulk_cp(wsm_u + (uint32_t)buf * (WTILE * 4) + wdst_off,
                    wt + wsrc0 + c * WC_STRIDE, WSEG_BYTES, mb);
        if (is_xst && xvalid)
            bulk_cp(xsm_u + (uint32_t)buf * (XTILE * 4) + xdst_off,
                    x + xsrc0 + c * XC_STRIDE, XROW_BYTES, mb);
    };

    // prologue: arm both barriers strictly before any bulk issues
    if (tid == 0) {
        mbar_init(mbar0, 1);
        mbar_init(mbar1, 1);
        mbar_expect_tx(mbar0, TXBYTES);
        mbar_expect_tx(mbar1, TXBYTES);
    }
    __syncthreads();
    issue_bulks(0);
    issue_bulks(1);

    ull acc2[4][4];
    #pragma unroll
    for (int oo = 0; oo < 4; oo++)
        #pragma unroll
        for (int bp = 0; bp < 4; bp++)
            acc2[oo][bp] = 0ull;

    for (int c = 0; c < Cc; c++) {
        const int cur = c & 1;
        mbar_wait(cur ? mbar1 : mbar0, (c >> 1) & 1);   // stage(c) complete (acquire)

        const float* wb = wsm + cur * WTILE + oq * 4 * SEG + w * Kk;
        const float* xb = xsm + cur * XTILE + 3 + w;

        #pragma unroll
        for (int r = 0; r < 3; r++) {
            ull wr2[4][3];
            #pragma unroll
            for (int oo = 0; oo < 4; oo++)
                #pragma unroll
                for (int kk = 0; kk < 3; kk++) {
                    float f = wb[oo * SEG + r * 3 + kk];
                    wr2[oo][kk] = pack2(f, f);
                }
            #pragma unroll
            for (int bp = 0; bp < 4; bp++) {
                const float* xlo = xb + (2 * bp)     * (XROWS * XCOLP) + r * XCOLP;
                const float* xhi = xb + (2 * bp + 1) * (XROWS * XCOLP) + r * XCOLP;
                ull xv2[3];
                #pragma unroll
                for (int kk = 0; kk < 3; kk++)
                    xv2[kk] = pack2(xlo[kk], xhi[kk]);
                #pragma unroll
                for (int oo = 0; oo < 4; oo++)
                    #pragma unroll
                    for (int kk = 0; kk < 3; kk++)
                        fma2(acc2[oo][bp], wr2[oo][kk], xv2[kk]);
            }
        }

        if (c + 2 < Cc) {
            // re-arm the consumed barrier BEFORE the CTA barrier that releases stagers
            if (tid == 0)
                mbar_expect_tx(cur ? mbar1 : mbar0, TXBYTES);
            __syncthreads();               // all threads done READING buffer `cur`
            issue_bulks(c + 2);            // refill just-consumed buffer
        }
    }

    // epilogue: coalesced stores
    float* op = out + ((size_t)o0 * Hh + h) * Ww + w;
    #pragma unroll
    for (int bp = 0; bp < 4; bp++)
        #pragma unroll
        for (int oo = 0; oo < 4; oo++) {
            float lo, hi;
            unpack2(lo, hi, acc2[oo][bp]);
            op[(size_t)((2 * bp)     * Oo + oo) * (Hh * Ww)] = lo;
            op[(size_t)((2 * bp + 1) * Oo + oo) * (Hh * Ww)] = hi;
        }
}

extern "C" void kernel_launch(void* const* d_in, const int* in_sizes, int n_in,
                              void* d_out, int out_size)
{
    const float* x  = (const float*)d_in[0];
    const float* wt = (const float*)d_in[1];
    float* out      = (float*)d_out;

    cudaFuncSetAttribute(lc2d_kernel,
                         cudaFuncAttributeMaxDynamicSharedMemorySize, SMEM_BYTES);
    cudaFuncSetAttribute(lc2d_kernel,
                         cudaFuncAttributePreferredSharedMemoryCarveout, 100);

    dim3 grid(Hh, Oo / OTILE);   // 64 x 4 = 256 blocks of 256 threads
    lc2d_kernel<<<grid, 256, SMEM_BYTES>>>(x, wt, out);
}